// round 14
// baseline (speedup 1.0000x reference)
#include <cuda_runtime.h>

#define BATCH 8
#define CDIM  256
#define HWDIM 1024
#define NNODE 102
#define GD    64
#define NH    8
#define HD    32
#define SCALE 0.17677669529663687f

typedef unsigned long long ull;

__device__ float    g_importance[BATCH * HWDIM];
__device__ int      g_topidx[BATCH * NNODE];
__device__ int      g_posmap[BATCH * HWDIM];
__device__ float    g_gw[BATCH * NNODE * NH];
__device__ unsigned g_adj[BATCH * NNODE * 4];
__device__ float    g_qkv[(size_t)BATCH * HWDIM * 768];
__device__ float    g_attnout[(size_t)BATCH * HWDIM * CDIM];

__device__ __forceinline__ float wrsum(float v) {
#pragma unroll
    for (int o = 16; o; o >>= 1) v += __shfl_xor_sync(0xffffffffu, v, o);
    return v;
}

// ---- packed f32x2 helpers (FFMA2: only reachable via PTX) ----
__device__ __forceinline__ ull fma2(ull a, ull b, ull c) {
    ull d;
    asm("fma.rn.f32x2 %0, %1, %2, %3;" : "=l"(d) : "l"(a), "l"(b), "l"(c));
    return d;
}
__device__ __forceinline__ ull add2(ull a, ull b) {
    ull d;
    asm("add.rn.f32x2 %0, %1, %2;" : "=l"(d) : "l"(a), "l"(b));
    return d;
}
__device__ __forceinline__ ull pack2(float x, float y) {
    ull d;
    asm("mov.b64 %0, {%1, %2};" : "=l"(d) : "f"(x), "f"(y));
    return d;
}
__device__ __forceinline__ float2 unpack2(ull v) {
    float x, y;
    asm("mov.b64 {%0, %1}, %2;" : "=f"(x), "=f"(y) : "l"(v));
    return make_float2(x, y);
}

// ---- 1) importance = channel variance (ordering only; constant factor dropped) ----
__global__ void imp_kernel(const float* __restrict__ x) {
    int b = blockIdx.y;
    int p = blockIdx.x * 256 + threadIdx.x;
    const float* xp = x + (size_t)b * CDIM * HWDIM + p;
    float s = 0.f;
    for (int c = 0; c < CDIM; c++) s += xp[c * HWDIM];
    float mean = s * (1.f / 256.f);
    float ss = 0.f;
    for (int c = 0; c < CDIM; c++) { float d = xp[c * HWDIM] - mean; ss += d * d; }
    g_importance[b * HWDIM + p] = ss;
}

// ---- 2) top-102 per batch via bitonic sort (descending) ----
__global__ void topk_kernel() {
    __shared__ float sv[1024];
    __shared__ int   si[1024];
    int b = blockIdx.x, tid = threadIdx.x;
    sv[tid] = g_importance[b * HWDIM + tid];
    si[tid] = tid;
    g_posmap[b * HWDIM + tid] = -1;
    __syncthreads();
    for (int k = 2; k <= 1024; k <<= 1)
        for (int j = k >> 1; j > 0; j >>= 1) {
            int ixj = tid ^ j;
            if (ixj > tid) {
                bool up = ((tid & k) == 0);
                float va = sv[tid], vb = sv[ixj];
                bool sw = up ? (va < vb) : (va > vb);
                if (sw) {
                    sv[tid] = vb; sv[ixj] = va;
                    int t = si[tid]; si[tid] = si[ixj]; si[ixj] = t;
                }
            }
            __syncthreads();
        }
    if (tid < NNODE) {
        g_topidx[b * NNODE + tid] = si[tid];
        g_posmap[b * HWDIM + si[tid]] = tid;
    }
}

// ---- 3) graph kernel: gather, adjacency, 2x GAT, gate ----
#define FS 257
#define GRAPH_SMEM ((104*FS + 104*64*2 + 104*3)*4 + 408*4 + 104*4)

template<int CIN, int ISTR>
__device__ __forceinline__ void gat_linear(const float* __restrict__ in,
                                           const float* __restrict__ W,
                                           float* __restrict__ out, int tid) {
    int f = tid & 63, grp = tid >> 6;
    for (int nb = grp * 8; nb < NNODE; nb += 32) {
        float acc[8] = {0,0,0,0,0,0,0,0};
        for (int c = 0; c < CIN; c++) {
            float w = __ldg(&W[c * GD + f]);
            const float* ip = in + c;
#pragma unroll
            for (int u = 0; u < 8; u++) acc[u] += ip[(nb + u) * ISTR] * w;
        }
#pragma unroll
        for (int u = 0; u < 8; u++)
            if (nb + u < NNODE) out[(nb + u) * GD + f] = acc[u];
    }
}

__device__ __forceinline__ void gat_srcdst(const float* __restrict__ h,
                                           const float* __restrict__ asw,
                                           const float* __restrict__ adw,
                                           float* __restrict__ vsrc, float* __restrict__ vdst,
                                           int wid, int lane) {
    for (int n = wid; n < NNODE; n += 8) {
        float h0 = h[n * GD + lane], h1 = h[n * GD + lane + 32];
        float ps = h0 * __ldg(&asw[lane]) + h1 * __ldg(&asw[lane + 32]);
        float pd = h0 * __ldg(&adw[lane]) + h1 * __ldg(&adw[lane + 32]);
        ps = wrsum(ps); pd = wrsum(pd);
        if (!lane) { vsrc[n] = ps; vdst[n] = pd; }
    }
}

__device__ __forceinline__ void gat_aggregate(const float* __restrict__ h,
                                              const float* __restrict__ vsrc,
                                              const float* __restrict__ vdst,
                                              const unsigned* __restrict__ adjb,
                                              const float* __restrict__ bias,
                                              float* __restrict__ out,
                                              int wid, int lane) {
    for (int n = wid; n < NNODE; n += 8) {
        float dn = vdst[n];
        unsigned r0 = adjb[n*4+0], r1 = adjb[n*4+1], r2 = adjb[n*4+2], r3 = adjb[n*4+3];
        float den = 0.f, a0 = 0.f, a1 = 0.f;
        for (int j = 0; j < NNODE; j++) {
            unsigned w = (j < 32) ? r0 : ((j < 64) ? r1 : ((j < 96) ? r2 : r3));
            if ((w >> (j & 31)) & 1u) {
                float lg = dn + vsrc[j];
                lg = lg > 0.f ? lg : 0.2f * lg;
                float e = __expf(lg);
                den += e;
                a0 += e * h[j * GD + lane];
                a1 += e * h[j * GD + lane + 32];
            }
        }
        float inv = 1.f / den;
        float o0 = a0 * inv + __ldg(&bias[lane]);
        float o1 = a1 * inv + __ldg(&bias[lane + 32]);
        out[n * GD + lane]      = fmaxf(o0, 0.f);
        out[n * GD + lane + 32] = fmaxf(o1, 0.f);
    }
}

__global__ __launch_bounds__(256)
void graph_kernel(const float* __restrict__ x,
                  const float* __restrict__ W0, const float* __restrict__ a0s,
                  const float* __restrict__ a0d, const float* __restrict__ b0,
                  const float* __restrict__ W1, const float* __restrict__ a1s,
                  const float* __restrict__ a1d, const float* __restrict__ b1,
                  const float* __restrict__ wg, const float* __restrict__ bg) {
    extern __shared__ float sm[];
    float* feats = sm;                         // 104 x FS
    float* hA    = sm + 104 * FS;
    float* hB    = hA + 104 * 64;
    float* norms = hB + 104 * 64;
    float* vsrc  = norms + 104;
    float* vdst  = vsrc + 104;
    unsigned* adjb = (unsigned*)(vdst + 104);  // 408
    int* tix = (int*)(adjb + 408);             // 104

    int b = blockIdx.x, tid = threadIdx.x, lane = tid & 31, wid = tid >> 5;

    for (int t = tid; t < NNODE; t += 256) tix[t] = g_topidx[b * NNODE + t];
    for (int t = tid; t < 408; t += 256) adjb[t] = 0u;
    __syncthreads();

    const float* xb = x + (size_t)b * CDIM * HWDIM;
    for (int t = tid; t < NNODE * CDIM; t += 256) {
        int n = t >> 8, c = t & 255;
        feats[n * FS + c] = xb[c * HWDIM + tix[n]];
    }
    __syncthreads();

    for (int n = wid; n < NNODE; n += 8) {
        float ss = 0.f;
        for (int c = lane; c < CDIM; c += 32) { float v = feats[n * FS + c]; ss += v * v; }
        ss = wrsum(ss);
        if (!lane) norms[n] = fmaxf(sqrtf(ss), 1e-12f);
    }
    __syncthreads();

    for (int t = tid; t < NNODE * NNODE; t += 256) {
        int i = t / NNODE, j = t - i * NNODE;
        if (j <= i) continue;
        const float* fi = feats + i * FS;
        const float* fj = feats + j * FS;
        float dot = 0.f;
        for (int c = 0; c < CDIM; c++) dot += fi[c] * fj[c];
        if (dot > 0.6f * norms[i] * norms[j]) {
            atomicOr(&adjb[i * 4 + (j >> 5)], 1u << (j & 31));
            atomicOr(&adjb[j * 4 + (i >> 5)], 1u << (i & 31));
        }
    }
    for (int t = tid; t < NNODE; t += 256)
        atomicOr(&adjb[t * 4 + (t >> 5)], 1u << (t & 31));
    __syncthreads();

    gat_linear<CDIM, FS>(feats, W0, hA, tid);               __syncthreads();
    gat_srcdst(hA, a0s, a0d, vsrc, vdst, wid, lane);        __syncthreads();
    gat_aggregate(hA, vsrc, vdst, adjb, b0, hB, wid, lane); __syncthreads();
    gat_linear<GD, GD>(hB, W1, hA, tid);                    __syncthreads();
    gat_srcdst(hA, a1s, a1d, vsrc, vdst, wid, lane);        __syncthreads();
    gat_aggregate(hA, vsrc, vdst, adjb, b1, hB, wid, lane); __syncthreads();

    for (int n = wid; n < NNODE; n += 8) {
        float v0 = hB[n * GD + lane], v1 = hB[n * GD + lane + 32];
#pragma unroll
        for (int hh = 0; hh < NH; hh++) {
            float p = v0 * __ldg(&wg[hh * GD + lane]) + v1 * __ldg(&wg[hh * GD + lane + 32]);
            p = wrsum(p);
            if (!lane)
                g_gw[(b * NNODE + n) * NH + hh] = 1.f / (1.f + __expf(-(p + __ldg(&bg[hh]))));
        }
    }
    for (int t = tid; t < 408; t += 256) g_adj[b * 408 + t] = adjb[t];
}

// ---- 4) QKV GEMM with packed f32x2 micro-kernel ----
__global__ __launch_bounds__(256)
void qkv_kernel(const float* __restrict__ x, const float* __restrict__ w) {
    __shared__ __align__(16) float As[16][64];
    __shared__ __align__(16) float Bs[16][68];
    int b = blockIdx.z;
    int p0 = blockIdx.x * 64, o0 = blockIdx.y * 64;
    int tid = threadIdx.x, tx = tid & 15, ty = tid >> 4;
    const float* xb = x + (size_t)b * CDIM * HWDIM;

    ull accp[2][4];   // packed over i-pairs x j
#pragma unroll
    for (int i = 0; i < 2; i++)
#pragma unroll
        for (int j = 0; j < 4; j++) accp[i][j] = 0ull;

    for (int c0 = 0; c0 < CDIM; c0 += 16) {
        {
            int c = tid >> 4, pv = (tid & 15) * 4;
            *(float4*)&As[c][pv] = *(const float4*)(xb + (size_t)(c0 + c) * HWDIM + p0 + pv);
        }
        {
            int o = tid >> 2, cv = (tid & 3) * 4;
            float4 wv = *(const float4*)(w + (size_t)(o0 + o) * CDIM + c0 + cv);
            Bs[cv + 0][o] = wv.x; Bs[cv + 1][o] = wv.y;
            Bs[cv + 2][o] = wv.z; Bs[cv + 3][o] = wv.w;
        }
        __syncthreads();
#pragma unroll
        for (int kk = 0; kk < 16; kk++) {
            ulonglong2 av2 = *(const ulonglong2*)&As[kk][tx * 4];  // (a0,a1),(a2,a3) free-packed
            float4 bv = *(const float4*)&Bs[kk][ty * 4];
            ull bp0 = pack2(bv.x, bv.x), bp1 = pack2(bv.y, bv.y);
            ull bp2 = pack2(bv.z, bv.z), bp3 = pack2(bv.w, bv.w);
            accp[0][0] = fma2(av2.x, bp0, accp[0][0]);
            accp[0][1] = fma2(av2.x, bp1, accp[0][1]);
            accp[0][2] = fma2(av2.x, bp2, accp[0][2]);
            accp[0][3] = fma2(av2.x, bp3, accp[0][3]);
            accp[1][0] = fma2(av2.y, bp0, accp[1][0]);
            accp[1][1] = fma2(av2.y, bp1, accp[1][1]);
            accp[1][2] = fma2(av2.y, bp2, accp[1][2]);
            accp[1][3] = fma2(av2.y, bp3, accp[1][3]);
        }
        __syncthreads();
    }
    float acc[4][4];
#pragma unroll
    for (int i2 = 0; i2 < 2; i2++)
#pragma unroll
        for (int j = 0; j < 4; j++) {
            float2 u = unpack2(accp[i2][j]);
            acc[2 * i2 + 0][j] = u.x;
            acc[2 * i2 + 1][j] = u.y;
        }
#pragma unroll
    for (int i = 0; i < 4; i++) {
        float4 st = make_float4(acc[i][0], acc[i][1], acc[i][2], acc[i][3]);
        *(float4*)(g_qkv + ((size_t)b * HWDIM + p0 + tx * 4 + i) * 768 + o0 + ty * 4) = st;
    }
}

// ---- 5) fused attention + graph modulation, packed f32x2 mainloop ----
#define TK 64
__global__ __launch_bounds__(128)
void attn_kernel() {
    __shared__ __align__(16) float Ks[TK * HD];
    __shared__ __align__(16) float Vs[TK * HD];
    __shared__ int   posk[TK];
    __shared__ float gwh[104];
    int b = blockIdx.z, h = blockIdx.y;
    int q0 = blockIdx.x * 256;
    int tid = threadIdx.x;
    int q1 = q0 + tid, q2 = q0 + 128 + tid;

    if (tid < NNODE) gwh[tid] = g_gw[(b * NNODE + tid) * NH + h];

    const float* qb = g_qkv + (size_t)b * HWDIM * 768;
    ull Q1p[16], Q2p[16], O1p[16], O2p[16];
    {
        const ulonglong2* p1 = (const ulonglong2*)(qb + (size_t)q1 * 768 + h * HD);
        const ulonglong2* p2 = (const ulonglong2*)(qb + (size_t)q2 * 768 + h * HD);
#pragma unroll
        for (int dd = 0; dd < 8; dd++) {
            ulonglong2 t1 = p1[dd]; Q1p[2*dd] = t1.x; Q1p[2*dd+1] = t1.y;
            ulonglong2 t2 = p2[dd]; Q2p[2*dd] = t2.x; Q2p[2*dd+1] = t2.y;
        }
    }
#pragma unroll
    for (int i = 0; i < 16; i++) { O1p[i] = 0ull; O2p[i] = 0ull; }

    int nq1 = g_posmap[b * HWDIM + q1];
    int nq2 = g_posmap[b * HWDIM + q2];
    __syncthreads();
    float gq1 = 0.f, gq2 = 0.f;
    unsigned A1[4] = {0,0,0,0}, A2[4] = {0,0,0,0};
    if (nq1 >= 0) {
        gq1 = gwh[nq1];
#pragma unroll
        for (int i = 0; i < 4; i++) A1[i] = g_adj[b * 408 + nq1 * 4 + i];
    }
    if (nq2 >= 0) {
        gq2 = gwh[nq2];
#pragma unroll
        for (int i = 0; i < 4; i++) A2[i] = g_adj[b * 408 + nq2 * 4 + i];
    }

    const float* kb = qb + 256 + h * HD;
    const float* vb = qb + 512 + h * HD;
    float l1 = 0.f, l2 = 0.f;

    for (int k0 = 0; k0 < HWDIM; k0 += TK) {
        __syncthreads();
#pragma unroll
        for (int u = 0; u < 4; u++) {
            int f4 = tid + u * 128;
            int r = f4 >> 3, dd = f4 & 7;
            ((float4*)Ks)[r * 8 + dd] = *(const float4*)(kb + (size_t)(k0 + r) * 768 + dd * 4);
            ((float4*)Vs)[r * 8 + dd] = *(const float4*)(vb + (size_t)(k0 + r) * 768 + dd * 4);
        }
        if (tid < TK) posk[tid] = g_posmap[b * HWDIM + k0 + tid];
        __syncthreads();

        for (int kk = 0; kk < TK; kk++) {
            const ulonglong2* K2 = (const ulonglong2*)(Ks + kk * HD);  // 8 x (2 packed pairs)
            ull a1 = 0ull, c1 = 0ull, a2 = 0ull, c2 = 0ull;
#pragma unroll
            for (int dd = 0; dd < 8; dd++) {
                ulonglong2 kv = K2[dd];
                a1 = fma2(Q1p[2*dd],   kv.x, a1);
                c1 = fma2(Q1p[2*dd+1], kv.y, c1);
                a2 = fma2(Q2p[2*dd],   kv.x, a2);
                c2 = fma2(Q2p[2*dd+1], kv.y, c2);
            }
            float2 f1 = unpack2(add2(a1, c1));
            float2 f2 = unpack2(add2(a2, c2));
            float s1 = (f1.x + f1.y) * SCALE;
            float s2 = (f2.x + f2.y) * SCALE;
            int nk = posk[kk];
            if (nk >= 0) {
                float gk = gwh[nk];
                unsigned w1 = (nk < 32) ? A1[0] : ((nk < 64) ? A1[1] : ((nk < 96) ? A1[2] : A1[3]));
                unsigned w2 = (nk < 32) ? A2[0] : ((nk < 64) ? A2[1] : ((nk < 96) ? A2[2] : A2[3]));
                if (nq1 >= 0 && ((w1 >> (nk & 31)) & 1u)) s1 += gq1 * gk;
                if (nq2 >= 0 && ((w2 >> (nk & 31)) & 1u)) s2 += gq2 * gk;
            }
            float e1 = __expf(s1), e2 = __expf(s2);   // |s| <= ~2.5: safe without max
            l1 += e1; l2 += e2;
            ull e1p = pack2(e1, e1), e2p = pack2(e2, e2);
            const ulonglong2* V2 = (const ulonglong2*)(Vs + kk * HD);
#pragma unroll
            for (int dd = 0; dd < 8; dd++) {
                ulonglong2 vv = V2[dd];
                O1p[2*dd]   = fma2(e1p, vv.x, O1p[2*dd]);
                O1p[2*dd+1] = fma2(e1p, vv.y, O1p[2*dd+1]);
                O2p[2*dd]   = fma2(e2p, vv.x, O2p[2*dd]);
                O2p[2*dd+1] = fma2(e2p, vv.y, O2p[2*dd+1]);
            }
        }
    }
    float inv1 = 1.f / l1, inv2 = 1.f / l2;
    float* o1p = g_attnout + ((size_t)b * HWDIM + q1) * CDIM + h * HD;
    float* o2p = g_attnout + ((size_t)b * HWDIM + q2) * CDIM + h * HD;
#pragma unroll
    for (int dd = 0; dd < 8; dd++) {
        float2 u0 = unpack2(O1p[2*dd]);
        float2 u1 = unpack2(O1p[2*dd+1]);
        *(float4*)(o1p + dd*4) = make_float4(u0.x*inv1, u0.y*inv1, u1.x*inv1, u1.y*inv1);
        float2 v0 = unpack2(O2p[2*dd]);
        float2 v1 = unpack2(O2p[2*dd+1]);
        *(float4*)(o2p + dd*4) = make_float4(v0.x*inv2, v0.y*inv2, v1.x*inv2, v1.y*inv2);
    }
}

// ---- 6) output projection (+bias), packed f32x2, output layout [B][C][HW] ----
__global__ __launch_bounds__(256)
void proj_kernel(const float* __restrict__ w, const float* __restrict__ bias,
                 float* __restrict__ out) {
    __shared__ __align__(16) float As[16][68];
    __shared__ __align__(16) float Bs[16][68];
    int b = blockIdx.z;
    int p0 = blockIdx.x * 64, o0 = blockIdx.y * 64;
    int tid = threadIdx.x, tx = tid & 15, ty = tid >> 4;
    const float* ab = g_attnout + (size_t)b * HWDIM * CDIM;

    ull accp[2][4];
#pragma unroll
    for (int i = 0; i < 2; i++)
#pragma unroll
        for (int j = 0; j < 4; j++) accp[i][j] = 0ull;

    for (int c0 = 0; c0 < CDIM; c0 += 16) {
        {
            int p = tid >> 2, cv = (tid & 3) * 4;
            float4 av = *(const float4*)(ab + (size_t)(p0 + p) * CDIM + c0 + cv);
            As[cv + 0][p] = av.x; As[cv + 1][p] = av.y;
            As[cv + 2][p] = av.z; As[cv + 3][p] = av.w;
        }
        {
            int o = tid >> 2, cv = (tid & 3) * 4;
            float4 wv = *(const float4*)(w + (size_t)(o0 + o) * CDIM + c0 + cv);
            Bs[cv + 0][o] = wv.x; Bs[cv + 1][o] = wv.y;
            Bs[cv + 2][o] = wv.z; Bs[cv + 3][o] = wv.w;
        }
        __syncthreads();
#pragma unroll
        for (int kk = 0; kk < 16; kk++) {
            ulonglong2 av2 = *(const ulonglong2*)&As[kk][tx * 4];
            float4 bv = *(const float4*)&Bs[kk][ty * 4];
            ull bp0 = pack2(bv.x, bv.x), bp1 = pack2(bv.y, bv.y);
            ull bp2 = pack2(bv.z, bv.z), bp3 = pack2(bv.w, bv.w);
            accp[0][0] = fma2(av2.x, bp0, accp[0][0]);
            accp[0][1] = fma2(av2.x, bp1, accp[0][1]);
            accp[0][2] = fma2(av2.x, bp2, accp[0][2]);
            accp[0][3] = fma2(av2.x, bp3, accp[0][3]);
            accp[1][0] = fma2(av2.y, bp0, accp[1][0]);
            accp[1][1] = fma2(av2.y, bp1, accp[1][1]);
            accp[1][2] = fma2(av2.y, bp2, accp[1][2]);
            accp[1][3] = fma2(av2.y, bp3, accp[1][3]);
        }
        __syncthreads();
    }
    float acc[4][4];
#pragma unroll
    for (int i2 = 0; i2 < 2; i2++)
#pragma unroll
        for (int j = 0; j < 4; j++) {
            float2 u = unpack2(accp[i2][j]);
            acc[2 * i2 + 0][j] = u.x;
            acc[2 * i2 + 1][j] = u.y;
        }
#pragma unroll
    for (int j = 0; j < 4; j++) {
        int o = o0 + ty * 4 + j;
        float bv = __ldg(&bias[o]);
        float4 st = make_float4(acc[0][j] + bv, acc[1][j] + bv, acc[2][j] + bv, acc[3][j] + bv);
        *(float4*)(out + ((size_t)b * CDIM + o) * HWDIM + p0 + tx * 4) = st;
    }
}

extern "C" void kernel_launch(void* const* d_in, const int* in_sizes, int n_in,
                              void* d_out, int out_size) {
    const float* x      = (const float*)d_in[0];
    const float* w_qkv  = (const float*)d_in[1];
    const float* w_proj = (const float*)d_in[2];
    const float* b_proj = (const float*)d_in[3];
    const float* g0W = (const float*)d_in[4];
    const float* g0s = (const float*)d_in[5];
    const float* g0d = (const float*)d_in[6];
    const float* g0b = (const float*)d_in[7];
    const float* g1W = (const float*)d_in[8];
    const float* g1s = (const float*)d_in[9];
    const float* g1d = (const float*)d_in[10];
    const float* g1b = (const float*)d_in[11];
    const float* wg  = (const float*)d_in[12];
    const float* bg  = (const float*)d_in[13];
    float* out = (float*)d_out;

    static bool attr_set = false;
    if (!attr_set) {
        cudaFuncSetAttribute(graph_kernel, cudaFuncAttributeMaxDynamicSharedMemorySize, GRAPH_SMEM);
        attr_set = true;
    }

    imp_kernel<<<dim3(HWDIM / 256, BATCH), 256>>>(x);
    topk_kernel<<<BATCH, 1024>>>();
    graph_kernel<<<BATCH, 256, GRAPH_SMEM>>>(x, g0W, g0s, g0d, g0b,
                                             g1W, g1s, g1d, g1b, wg, bg);
    qkv_kernel<<<dim3(HWDIM / 64, 768 / 64, BATCH), 256>>>(x, w_qkv);
    attn_kernel<<<dim3(HWDIM / 256, NH, BATCH), 128>>>();
    proj_kernel<<<dim3(HWDIM / 64, CDIM / 64, BATCH), 256>>>(w_proj, b_proj, out);
}

// round 15
// speedup vs baseline: 1.6227x; 1.6227x over previous
#include <cuda_runtime.h>

#define BATCH 8
#define CDIM  256
#define HWDIM 1024
#define NNODE 102
#define GD    64
#define NH    8
#define HD    32
#define SCALE 0.17677669529663687f

typedef unsigned long long ull;

__device__ float    g_importance[BATCH * HWDIM];
__device__ int      g_topidx[BATCH * NNODE];
__device__ int      g_posmap[BATCH * HWDIM];
__device__ float    g_gw[BATCH * NNODE * NH];
__device__ unsigned g_adj[BATCH * NNODE * 4];
__device__ float    g_qkv[(size_t)BATCH * HWDIM * 768];
__device__ float    g_attnout[(size_t)BATCH * HWDIM * CDIM];

__device__ __forceinline__ float wrsum(float v) {
#pragma unroll
    for (int o = 16; o; o >>= 1) v += __shfl_xor_sync(0xffffffffu, v, o);
    return v;
}

// ---- packed f32x2 helpers (FFMA2: only reachable via PTX) ----
__device__ __forceinline__ ull fma2(ull a, ull b, ull c) {
    ull d;
    asm("fma.rn.f32x2 %0, %1, %2, %3;" : "=l"(d) : "l"(a), "l"(b), "l"(c));
    return d;
}
__device__ __forceinline__ ull add2(ull a, ull b) {
    ull d;
    asm("add.rn.f32x2 %0, %1, %2;" : "=l"(d) : "l"(a), "l"(b));
    return d;
}
__device__ __forceinline__ ull pack2(float x, float y) {
    ull d;
    asm("mov.b64 %0, {%1, %2};" : "=l"(d) : "f"(x), "f"(y));
    return d;
}
__device__ __forceinline__ float2 unpack2(ull v) {
    float x, y;
    asm("mov.b64 {%0, %1}, %2;" : "=f"(x), "=f"(y) : "l"(v));
    return make_float2(x, y);
}

// ---- 1) importance = channel variance (ordering only; constant factor dropped) ----
__global__ void imp_kernel(const float* __restrict__ x) {
    int b = blockIdx.y;
    int p = blockIdx.x * 256 + threadIdx.x;
    const float* xp = x + (size_t)b * CDIM * HWDIM + p;
    float s = 0.f;
    for (int c = 0; c < CDIM; c++) s += xp[c * HWDIM];
    float mean = s * (1.f / 256.f);
    float ss = 0.f;
    for (int c = 0; c < CDIM; c++) { float d = xp[c * HWDIM] - mean; ss += d * d; }
    g_importance[b * HWDIM + p] = ss;
}

// ---- 2) top-102 per batch via bitonic sort (descending) ----
__global__ void topk_kernel() {
    __shared__ float sv[1024];
    __shared__ int   si[1024];
    int b = blockIdx.x, tid = threadIdx.x;
    sv[tid] = g_importance[b * HWDIM + tid];
    si[tid] = tid;
    g_posmap[b * HWDIM + tid] = -1;
    __syncthreads();
    for (int k = 2; k <= 1024; k <<= 1)
        for (int j = k >> 1; j > 0; j >>= 1) {
            int ixj = tid ^ j;
            if (ixj > tid) {
                bool up = ((tid & k) == 0);
                float va = sv[tid], vb = sv[ixj];
                bool sw = up ? (va < vb) : (va > vb);
                if (sw) {
                    sv[tid] = vb; sv[ixj] = va;
                    int t = si[tid]; si[tid] = si[ixj]; si[ixj] = t;
                }
            }
            __syncthreads();
        }
    if (tid < NNODE) {
        g_topidx[b * NNODE + tid] = si[tid];
        g_posmap[b * HWDIM + si[tid]] = tid;
    }
}

// ---- 3) graph kernel: gather, adjacency, 2x GAT, gate ----
#define FS 257
#define GRAPH_SMEM ((104*FS + 104*64*2 + 104*3)*4 + 408*4 + 104*4)

template<int CIN, int ISTR>
__device__ __forceinline__ void gat_linear(const float* __restrict__ in,
                                           const float* __restrict__ W,
                                           float* __restrict__ out, int tid) {
    int f = tid & 63, grp = tid >> 6;
    for (int nb = grp * 8; nb < NNODE; nb += 32) {
        float acc[8] = {0,0,0,0,0,0,0,0};
        for (int c = 0; c < CIN; c++) {
            float w = __ldg(&W[c * GD + f]);
            const float* ip = in + c;
#pragma unroll
            for (int u = 0; u < 8; u++) acc[u] += ip[(nb + u) * ISTR] * w;
        }
#pragma unroll
        for (int u = 0; u < 8; u++)
            if (nb + u < NNODE) out[(nb + u) * GD + f] = acc[u];
    }
}

__device__ __forceinline__ void gat_srcdst(const float* __restrict__ h,
                                           const float* __restrict__ asw,
                                           const float* __restrict__ adw,
                                           float* __restrict__ vsrc, float* __restrict__ vdst,
                                           int wid, int lane) {
    for (int n = wid; n < NNODE; n += 8) {
        float h0 = h[n * GD + lane], h1 = h[n * GD + lane + 32];
        float ps = h0 * __ldg(&asw[lane]) + h1 * __ldg(&asw[lane + 32]);
        float pd = h0 * __ldg(&adw[lane]) + h1 * __ldg(&adw[lane + 32]);
        ps = wrsum(ps); pd = wrsum(pd);
        if (!lane) { vsrc[n] = ps; vdst[n] = pd; }
    }
}

__device__ __forceinline__ void gat_aggregate(const float* __restrict__ h,
                                              const float* __restrict__ vsrc,
                                              const float* __restrict__ vdst,
                                              const unsigned* __restrict__ adjb,
                                              const float* __restrict__ bias,
                                              float* __restrict__ out,
                                              int wid, int lane) {
    for (int n = wid; n < NNODE; n += 8) {
        float dn = vdst[n];
        unsigned r0 = adjb[n*4+0], r1 = adjb[n*4+1], r2 = adjb[n*4+2], r3 = adjb[n*4+3];
        float den = 0.f, a0 = 0.f, a1 = 0.f;
        for (int j = 0; j < NNODE; j++) {
            unsigned w = (j < 32) ? r0 : ((j < 64) ? r1 : ((j < 96) ? r2 : r3));
            if ((w >> (j & 31)) & 1u) {
                float lg = dn + vsrc[j];
                lg = lg > 0.f ? lg : 0.2f * lg;
                float e = __expf(lg);
                den += e;
                a0 += e * h[j * GD + lane];
                a1 += e * h[j * GD + lane + 32];
            }
        }
        float inv = 1.f / den;
        float o0 = a0 * inv + __ldg(&bias[lane]);
        float o1 = a1 * inv + __ldg(&bias[lane + 32]);
        out[n * GD + lane]      = fmaxf(o0, 0.f);
        out[n * GD + lane + 32] = fmaxf(o1, 0.f);
    }
}

__global__ __launch_bounds__(256)
void graph_kernel(const float* __restrict__ x,
                  const float* __restrict__ W0, const float* __restrict__ a0s,
                  const float* __restrict__ a0d, const float* __restrict__ b0,
                  const float* __restrict__ W1, const float* __restrict__ a1s,
                  const float* __restrict__ a1d, const float* __restrict__ b1,
                  const float* __restrict__ wg, const float* __restrict__ bg) {
    extern __shared__ float sm[];
    float* feats = sm;                         // 104 x FS
    float* hA    = sm + 104 * FS;
    float* hB    = hA + 104 * 64;
    float* norms = hB + 104 * 64;
    float* vsrc  = norms + 104;
    float* vdst  = vsrc + 104;
    unsigned* adjb = (unsigned*)(vdst + 104);  // 408
    int* tix = (int*)(adjb + 408);             // 104

    int b = blockIdx.x, tid = threadIdx.x, lane = tid & 31, wid = tid >> 5;

    for (int t = tid; t < NNODE; t += 256) tix[t] = g_topidx[b * NNODE + t];
    for (int t = tid; t < 408; t += 256) adjb[t] = 0u;
    __syncthreads();

    const float* xb = x + (size_t)b * CDIM * HWDIM;
    for (int t = tid; t < NNODE * CDIM; t += 256) {
        int n = t >> 8, c = t & 255;
        feats[n * FS + c] = xb[c * HWDIM + tix[n]];
    }
    __syncthreads();

    for (int n = wid; n < NNODE; n += 8) {
        float ss = 0.f;
        for (int c = lane; c < CDIM; c += 32) { float v = feats[n * FS + c]; ss += v * v; }
        ss = wrsum(ss);
        if (!lane) norms[n] = fmaxf(sqrtf(ss), 1e-12f);
    }
    __syncthreads();

    for (int t = tid; t < NNODE * NNODE; t += 256) {
        int i = t / NNODE, j = t - i * NNODE;
        if (j <= i) continue;
        const float* fi = feats + i * FS;
        const float* fj = feats + j * FS;
        float dot = 0.f;
        for (int c = 0; c < CDIM; c++) dot += fi[c] * fj[c];
        if (dot > 0.6f * norms[i] * norms[j]) {
            atomicOr(&adjb[i * 4 + (j >> 5)], 1u << (j & 31));
            atomicOr(&adjb[j * 4 + (i >> 5)], 1u << (i & 31));
        }
    }
    for (int t = tid; t < NNODE; t += 256)
        atomicOr(&adjb[t * 4 + (t >> 5)], 1u << (t & 31));
    __syncthreads();

    gat_linear<CDIM, FS>(feats, W0, hA, tid);               __syncthreads();
    gat_srcdst(hA, a0s, a0d, vsrc, vdst, wid, lane);        __syncthreads();
    gat_aggregate(hA, vsrc, vdst, adjb, b0, hB, wid, lane); __syncthreads();
    gat_linear<GD, GD>(hB, W1, hA, tid);                    __syncthreads();
    gat_srcdst(hA, a1s, a1d, vsrc, vdst, wid, lane);        __syncthreads();
    gat_aggregate(hA, vsrc, vdst, adjb, b1, hB, wid, lane); __syncthreads();

    for (int n = wid; n < NNODE; n += 8) {
        float v0 = hB[n * GD + lane], v1 = hB[n * GD + lane + 32];
#pragma unroll
        for (int hh = 0; hh < NH; hh++) {
            float p = v0 * __ldg(&wg[hh * GD + lane]) + v1 * __ldg(&wg[hh * GD + lane + 32]);
            p = wrsum(p);
            if (!lane)
                g_gw[(b * NNODE + n) * NH + hh] = 1.f / (1.f + __expf(-(p + __ldg(&bg[hh]))));
        }
    }
    for (int t = tid; t < 408; t += 256) g_adj[b * 408 + t] = adjb[t];
}

// ---- 4) QKV GEMM with packed f32x2 micro-kernel ----
__global__ __launch_bounds__(256)
void qkv_kernel(const float* __restrict__ x, const float* __restrict__ w) {
    __shared__ __align__(16) float As[16][64];
    __shared__ __align__(16) float Bs[16][68];
    int b = blockIdx.z;
    int p0 = blockIdx.x * 64, o0 = blockIdx.y * 64;
    int tid = threadIdx.x, tx = tid & 15, ty = tid >> 4;
    const float* xb = x + (size_t)b * CDIM * HWDIM;

    ull accp[2][4];   // packed over i-pairs x j
#pragma unroll
    for (int i = 0; i < 2; i++)
#pragma unroll
        for (int j = 0; j < 4; j++) accp[i][j] = 0ull;

    for (int c0 = 0; c0 < CDIM; c0 += 16) {
        {
            int c = tid >> 4, pv = (tid & 15) * 4;
            *(float4*)&As[c][pv] = *(const float4*)(xb + (size_t)(c0 + c) * HWDIM + p0 + pv);
        }
        {
            int o = tid >> 2, cv = (tid & 3) * 4;
            float4 wv = *(const float4*)(w + (size_t)(o0 + o) * CDIM + c0 + cv);
            Bs[cv + 0][o] = wv.x; Bs[cv + 1][o] = wv.y;
            Bs[cv + 2][o] = wv.z; Bs[cv + 3][o] = wv.w;
        }
        __syncthreads();
#pragma unroll
        for (int kk = 0; kk < 16; kk++) {
            ulonglong2 av2 = *(const ulonglong2*)&As[kk][tx * 4];  // (a0,a1),(a2,a3) free-packed
            float4 bv = *(const float4*)&Bs[kk][ty * 4];
            ull bp0 = pack2(bv.x, bv.x), bp1 = pack2(bv.y, bv.y);
            ull bp2 = pack2(bv.z, bv.z), bp3 = pack2(bv.w, bv.w);
            accp[0][0] = fma2(av2.x, bp0, accp[0][0]);
            accp[0][1] = fma2(av2.x, bp1, accp[0][1]);
            accp[0][2] = fma2(av2.x, bp2, accp[0][2]);
            accp[0][3] = fma2(av2.x, bp3, accp[0][3]);
            accp[1][0] = fma2(av2.y, bp0, accp[1][0]);
            accp[1][1] = fma2(av2.y, bp1, accp[1][1]);
            accp[1][2] = fma2(av2.y, bp2, accp[1][2]);
            accp[1][3] = fma2(av2.y, bp3, accp[1][3]);
        }
        __syncthreads();
    }
    float acc[4][4];
#pragma unroll
    for (int i2 = 0; i2 < 2; i2++)
#pragma unroll
        for (int j = 0; j < 4; j++) {
            float2 u = unpack2(accp[i2][j]);
            acc[2 * i2 + 0][j] = u.x;
            acc[2 * i2 + 1][j] = u.y;
        }
#pragma unroll
    for (int i = 0; i < 4; i++) {
        float4 st = make_float4(acc[i][0], acc[i][1], acc[i][2], acc[i][3]);
        *(float4*)(g_qkv + ((size_t)b * HWDIM + p0 + tx * 4 + i) * 768 + o0 + ty * 4) = st;
    }
}

// ---- 5) fused attention + graph modulation, packed f32x2 mainloop ----
#define TK 64
__global__ __launch_bounds__(128)
void attn_kernel() {
    __shared__ __align__(16) float Ks[TK * HD];
    __shared__ __align__(16) float Vs[TK * HD];
    __shared__ int   posk[TK];
    __shared__ float gwh[104];
    int b = blockIdx.z, h = blockIdx.y;
    int q0 = blockIdx.x * 256;
    int tid = threadIdx.x;
    int q1 = q0 + tid, q2 = q0 + 128 + tid;

    if (tid < NNODE) gwh[tid] = g_gw[(b * NNODE + tid) * NH + h];

    const float* qb = g_qkv + (size_t)b * HWDIM * 768;
    ull Q1p[16], Q2p[16], O1p[16], O2p[16];
    {
        const ulonglong2* p1 = (const ulonglong2*)(qb + (size_t)q1 * 768 + h * HD);
        const ulonglong2* p2 = (const ulonglong2*)(qb + (size_t)q2 * 768 + h * HD);
#pragma unroll
        for (int dd = 0; dd < 8; dd++) {
            ulonglong2 t1 = p1[dd]; Q1p[2*dd] = t1.x; Q1p[2*dd+1] = t1.y;
            ulonglong2 t2 = p2[dd]; Q2p[2*dd] = t2.x; Q2p[2*dd+1] = t2.y;
        }
    }
#pragma unroll
    for (int i = 0; i < 16; i++) { O1p[i] = 0ull; O2p[i] = 0ull; }

    int nq1 = g_posmap[b * HWDIM + q1];
    int nq2 = g_posmap[b * HWDIM + q2];
    __syncthreads();
    float gq1 = 0.f, gq2 = 0.f;
    unsigned A1[4] = {0,0,0,0}, A2[4] = {0,0,0,0};
    if (nq1 >= 0) {
        gq1 = gwh[nq1];
#pragma unroll
        for (int i = 0; i < 4; i++) A1[i] = g_adj[b * 408 + nq1 * 4 + i];
    }
    if (nq2 >= 0) {
        gq2 = gwh[nq2];
#pragma unroll
        for (int i = 0; i < 4; i++) A2[i] = g_adj[b * 408 + nq2 * 4 + i];
    }

    const float* kb = qb + 256 + h * HD;
    const float* vb = qb + 512 + h * HD;
    float l1 = 0.f, l2 = 0.f;

    for (int k0 = 0; k0 < HWDIM; k0 += TK) {
        __syncthreads();
#pragma unroll
        for (int u = 0; u < 4; u++) {
            int f4 = tid + u * 128;
            int r = f4 >> 3, dd = f4 & 7;
            ((float4*)Ks)[r * 8 + dd] = *(const float4*)(kb + (size_t)(k0 + r) * 768 + dd * 4);
            ((float4*)Vs)[r * 8 + dd] = *(const float4*)(vb + (size_t)(k0 + r) * 768 + dd * 4);
        }
        if (tid < TK) posk[tid] = g_posmap[b * HWDIM + k0 + tid];
        __syncthreads();

        for (int kk = 0; kk < TK; kk++) {
            const ulonglong2* K2 = (const ulonglong2*)(Ks + kk * HD);  // 8 x (2 packed pairs)
            ull a1 = 0ull, c1 = 0ull, a2 = 0ull, c2 = 0ull;
#pragma unroll
            for (int dd = 0; dd < 8; dd++) {
                ulonglong2 kv = K2[dd];
                a1 = fma2(Q1p[2*dd],   kv.x, a1);
                c1 = fma2(Q1p[2*dd+1], kv.y, c1);
                a2 = fma2(Q2p[2*dd],   kv.x, a2);
                c2 = fma2(Q2p[2*dd+1], kv.y, c2);
            }
            float2 f1 = unpack2(add2(a1, c1));
            float2 f2 = unpack2(add2(a2, c2));
            float s1 = (f1.x + f1.y) * SCALE;
            float s2 = (f2.x + f2.y) * SCALE;
            int nk = posk[kk];
            if (nk >= 0) {
                float gk = gwh[nk];
                unsigned w1 = (nk < 32) ? A1[0] : ((nk < 64) ? A1[1] : ((nk < 96) ? A1[2] : A1[3]));
                unsigned w2 = (nk < 32) ? A2[0] : ((nk < 64) ? A2[1] : ((nk < 96) ? A2[2] : A2[3]));
                if (nq1 >= 0 && ((w1 >> (nk & 31)) & 1u)) s1 += gq1 * gk;
                if (nq2 >= 0 && ((w2 >> (nk & 31)) & 1u)) s2 += gq2 * gk;
            }
            float e1 = __expf(s1), e2 = __expf(s2);   // |s| <= ~2.5: safe without max
            l1 += e1; l2 += e2;
            ull e1p = pack2(e1, e1), e2p = pack2(e2, e2);
            const ulonglong2* V2 = (const ulonglong2*)(Vs + kk * HD);
#pragma unroll
            for (int dd = 0; dd < 8; dd++) {
                ulonglong2 vv = V2[dd];
                O1p[2*dd]   = fma2(e1p, vv.x, O1p[2*dd]);
                O1p[2*dd+1] = fma2(e1p, vv.y, O1p[2*dd+1]);
                O2p[2*dd]   = fma2(e2p, vv.x, O2p[2*dd]);
                O2p[2*dd+1] = fma2(e2p, vv.y, O2p[2*dd+1]);
            }
        }
    }
    float inv1 = 1.f / l1, inv2 = 1.f / l2;
    float* o1p = g_attnout + ((size_t)b * HWDIM + q1) * CDIM + h * HD;
    float* o2p = g_attnout + ((size_t)b * HWDIM + q2) * CDIM + h * HD;
#pragma unroll
    for (int dd = 0; dd < 8; dd++) {
        float2 u0 = unpack2(O1p[2*dd]);
        float2 u1 = unpack2(O1p[2*dd+1]);
        *(float4*)(o1p + dd*4) = make_float4(u0.x*inv1, u0.y*inv1, u1.x*inv1, u1.y*inv1);
        float2 v0 = unpack2(O2p[2*dd]);
        float2 v1 = unpack2(O2p[2*dd+1]);
        *(float4*)(o2p + dd*4) = make_float4(v0.x*inv2, v0.y*inv2, v1.x*inv2, v1.y*inv2);
    }
}

// ---- 6) output projection (+bias), packed f32x2, output layout [B][C][HW] ----
__global__ __launch_bounds__(256)
void proj_kernel(const float* __restrict__ w, const float* __restrict__ bias,
                 float* __restrict__ out) {
    __shared__ __align__(16) float As[16][68];
    __shared__ __align__(16) float Bs[16][68];
    int b = blockIdx.z;
    int p0 = blockIdx.x * 64, o0 = blockIdx.y * 64;
    int tid = threadIdx.x, tx = tid & 15, ty = tid >> 4;
    const float* ab = g_attnout + (size_t)b * HWDIM * CDIM;

    ull accp[2][4];
#pragma unroll
    for (int i = 0; i < 2; i++)
#pragma unroll
        for (int j = 0; j < 4; j++) accp[i][j] = 0ull;

    for (int c0 = 0; c0 < CDIM; c0 += 16) {
        {
            int p = tid >> 2, cv = (tid & 3) * 4;
            float4 av = *(const float4*)(ab + (size_t)(p0 + p) * CDIM + c0 + cv);
            As[cv + 0][p] = av.x; As[cv + 1][p] = av.y;
            As[cv + 2][p] = av.z; As[cv + 3][p] = av.w;
        }
        {
            int o = tid >> 2, cv = (tid & 3) * 4;
            float4 wv = *(const float4*)(w + (size_t)(o0 + o) * CDIM + c0 + cv);
            Bs[cv + 0][o] = wv.x; Bs[cv + 1][o] = wv.y;
            Bs[cv + 2][o] = wv.z; Bs[cv + 3][o] = wv.w;
        }
        __syncthreads();
#pragma unroll
        for (int kk = 0; kk < 16; kk++) {
            ulonglong2 av2 = *(const ulonglong2*)&As[kk][tx * 4];
            float4 bv = *(const float4*)&Bs[kk][ty * 4];
            ull bp0 = pack2(bv.x, bv.x), bp1 = pack2(bv.y, bv.y);
            ull bp2 = pack2(bv.z, bv.z), bp3 = pack2(bv.w, bv.w);
            accp[0][0] = fma2(av2.x, bp0, accp[0][0]);
            accp[0][1] = fma2(av2.x, bp1, accp[0][1]);
            accp[0][2] = fma2(av2.x, bp2, accp[0][2]);
            accp[0][3] = fma2(av2.x, bp3, accp[0][3]);
            accp[1][0] = fma2(av2.y, bp0, accp[1][0]);
            accp[1][1] = fma2(av2.y, bp1, accp[1][1]);
            accp[1][2] = fma2(av2.y, bp2, accp[1][2]);
            accp[1][3] = fma2(av2.y, bp3, accp[1][3]);
        }
        __syncthreads();
    }
    float acc[4][4];
#pragma unroll
    for (int i2 = 0; i2 < 2; i2++)
#pragma unroll
        for (int j = 0; j < 4; j++) {
            float2 u = unpack2(accp[i2][j]);
            acc[2 * i2 + 0][j] = u.x;
            acc[2 * i2 + 1][j] = u.y;
        }
#pragma unroll
    for (int j = 0; j < 4; j++) {
        int o = o0 + ty * 4 + j;
        float bv = __ldg(&bias[o]);
        float4 st = make_float4(acc[0][j] + bv, acc[1][j] + bv, acc[2][j] + bv, acc[3][j] + bv);
        *(float4*)(out + ((size_t)b * CDIM + o) * HWDIM + p0 + tx * 4) = st;
    }
}

extern "C" void kernel_launch(void* const* d_in, const int* in_sizes, int n_in,
                              void* d_out, int out_size) {
    const float* x      = (const float*)d_in[0];
    const float* w_qkv  = (const float*)d_in[1];
    const float* w_proj = (const float*)d_in[2];
    const float* b_proj = (const float*)d_in[3];
    const float* g0W = (const float*)d_in[4];
    const float* g0s = (const float*)d_in[5];
    const float* g0d = (const float*)d_in[6];
    const float* g0b = (const float*)d_in[7];
    const float* g1W = (const float*)d_in[8];
    const float* g1s = (const float*)d_in[9];
    const float* g1d = (const float*)d_in[10];
    const float* g1b = (const float*)d_in[11];
    const float* wg  = (const float*)d_in[12];
    const float* bg  = (const float*)d_in[13];
    float* out = (float*)d_out;

    static bool attr_set = false;
    if (!attr_set) {
        cudaFuncSetAttribute(graph_kernel, cudaFuncAttributeMaxDynamicSharedMemorySize, GRAPH_SMEM);
        attr_set = true;
    }

    imp_kernel<<<dim3(HWDIM / 256, BATCH), 256>>>(x);
    topk_kernel<<<BATCH, 1024>>>();
    graph_kernel<<<BATCH, 256, GRAPH_SMEM>>>(x, g0W, g0s, g0d, g0b,
                                             g1W, g1s, g1d, g1b, wg, bg);
    qkv_kernel<<<dim3(HWDIM / 64, 768 / 64, BATCH), 256>>>(x, w_qkv);
    attn_kernel<<<dim3(HWDIM / 256, NH, BATCH), 128>>>();
    proj_kernel<<<dim3(HWDIM / 64, CDIM / 64, BATCH), 256>>>(w_proj, b_proj, out);
}

// round 16
// speedup vs baseline: 1.6247x; 1.0012x over previous
#include <cuda_runtime.h>

#define BATCH 8
#define CDIM  256
#define HWDIM 1024
#define NNODE 102
#define GD    64
#define NH    8
#define HD    32
#define SCALE 0.17677669529663687f

typedef unsigned long long ull;

__device__ float    g_importance[BATCH * HWDIM];
__device__ int      g_topidx[BATCH * NNODE];
__device__ int      g_posmap[BATCH * HWDIM];
__device__ float    g_gw[BATCH * NNODE * NH];
__device__ unsigned g_adj[BATCH * NNODE * 4];
__device__ float    g_qkv[(size_t)BATCH * HWDIM * 768];
__device__ float    g_attnout[(size_t)BATCH * HWDIM * CDIM];

__device__ __forceinline__ float wrsum(float v) {
#pragma unroll
    for (int o = 16; o; o >>= 1) v += __shfl_xor_sync(0xffffffffu, v, o);
    return v;
}

// ---- packed f32x2 helpers (FFMA2: only reachable via PTX) ----
__device__ __forceinline__ ull fma2(ull a, ull b, ull c) {
    ull d;
    asm("fma.rn.f32x2 %0, %1, %2, %3;" : "=l"(d) : "l"(a), "l"(b), "l"(c));
    return d;
}
__device__ __forceinline__ ull add2(ull a, ull b) {
    ull d;
    asm("add.rn.f32x2 %0, %1, %2;" : "=l"(d) : "l"(a), "l"(b));
    return d;
}
__device__ __forceinline__ ull pack2(float x, float y) {
    ull d;
    asm("mov.b64 %0, {%1, %2};" : "=l"(d) : "f"(x), "f"(y));
    return d;
}
__device__ __forceinline__ float2 unpack2(ull v) {
    float x, y;
    asm("mov.b64 {%0, %1}, %2;" : "=f"(x), "=f"(y) : "l"(v));
    return make_float2(x, y);
}

// ---- 1) importance = channel variance (ordering only; constant factor dropped) ----
__global__ void imp_kernel(const float* __restrict__ x) {
    int b = blockIdx.y;
    int p = blockIdx.x * 256 + threadIdx.x;
    const float* xp = x + (size_t)b * CDIM * HWDIM + p;
    float s = 0.f;
    for (int c = 0; c < CDIM; c++) s += xp[c * HWDIM];
    float mean = s * (1.f / 256.f);
    float ss = 0.f;
    for (int c = 0; c < CDIM; c++) { float d = xp[c * HWDIM] - mean; ss += d * d; }
    g_importance[b * HWDIM + p] = ss;
}

// ---- 2) top-102 per batch via bitonic sort (descending) ----
__global__ void topk_kernel() {
    __shared__ float sv[1024];
    __shared__ int   si[1024];
    int b = blockIdx.x, tid = threadIdx.x;
    sv[tid] = g_importance[b * HWDIM + tid];
    si[tid] = tid;
    g_posmap[b * HWDIM + tid] = -1;
    __syncthreads();
    for (int k = 2; k <= 1024; k <<= 1)
        for (int j = k >> 1; j > 0; j >>= 1) {
            int ixj = tid ^ j;
            if (ixj > tid) {
                bool up = ((tid & k) == 0);
                float va = sv[tid], vb = sv[ixj];
                bool sw = up ? (va < vb) : (va > vb);
                if (sw) {
                    sv[tid] = vb; sv[ixj] = va;
                    int t = si[tid]; si[tid] = si[ixj]; si[ixj] = t;
                }
            }
            __syncthreads();
        }
    if (tid < NNODE) {
        g_topidx[b * NNODE + tid] = si[tid];
        g_posmap[b * HWDIM + si[tid]] = tid;
    }
}

// ---- 3) graph kernel: gather, adjacency, 2x GAT, gate ----
#define FS 257
#define GRAPH_SMEM ((104*FS + 104*64*2 + 104*3)*4 + 408*4 + 104*4)

template<int CIN, int ISTR>
__device__ __forceinline__ void gat_linear(const float* __restrict__ in,
                                           const float* __restrict__ W,
                                           float* __restrict__ out, int tid) {
    int f = tid & 63, grp = tid >> 6;
    for (int nb = grp * 8; nb < NNODE; nb += 32) {
        float acc[8] = {0,0,0,0,0,0,0,0};
        for (int c = 0; c < CIN; c++) {
            float w = __ldg(&W[c * GD + f]);
            const float* ip = in + c;
#pragma unroll
            for (int u = 0; u < 8; u++) acc[u] += ip[(nb + u) * ISTR] * w;
        }
#pragma unroll
        for (int u = 0; u < 8; u++)
            if (nb + u < NNODE) out[(nb + u) * GD + f] = acc[u];
    }
}

__device__ __forceinline__ void gat_srcdst(const float* __restrict__ h,
                                           const float* __restrict__ asw,
                                           const float* __restrict__ adw,
                                           float* __restrict__ vsrc, float* __restrict__ vdst,
                                           int wid, int lane) {
    for (int n = wid; n < NNODE; n += 8) {
        float h0 = h[n * GD + lane], h1 = h[n * GD + lane + 32];
        float ps = h0 * __ldg(&asw[lane]) + h1 * __ldg(&asw[lane + 32]);
        float pd = h0 * __ldg(&adw[lane]) + h1 * __ldg(&adw[lane + 32]);
        ps = wrsum(ps); pd = wrsum(pd);
        if (!lane) { vsrc[n] = ps; vdst[n] = pd; }
    }
}

__device__ __forceinline__ void gat_aggregate(const float* __restrict__ h,
                                              const float* __restrict__ vsrc,
                                              const float* __restrict__ vdst,
                                              const unsigned* __restrict__ adjb,
                                              const float* __restrict__ bias,
                                              float* __restrict__ out,
                                              int wid, int lane) {
    for (int n = wid; n < NNODE; n += 8) {
        float dn = vdst[n];
        unsigned r0 = adjb[n*4+0], r1 = adjb[n*4+1], r2 = adjb[n*4+2], r3 = adjb[n*4+3];
        float den = 0.f, a0 = 0.f, a1 = 0.f;
        for (int j = 0; j < NNODE; j++) {
            unsigned w = (j < 32) ? r0 : ((j < 64) ? r1 : ((j < 96) ? r2 : r3));
            if ((w >> (j & 31)) & 1u) {
                float lg = dn + vsrc[j];
                lg = lg > 0.f ? lg : 0.2f * lg;
                float e = __expf(lg);
                den += e;
                a0 += e * h[j * GD + lane];
                a1 += e * h[j * GD + lane + 32];
            }
        }
        float inv = 1.f / den;
        float o0 = a0 * inv + __ldg(&bias[lane]);
        float o1 = a1 * inv + __ldg(&bias[lane + 32]);
        out[n * GD + lane]      = fmaxf(o0, 0.f);
        out[n * GD + lane + 32] = fmaxf(o1, 0.f);
    }
}

__global__ __launch_bounds__(256)
void graph_kernel(const float* __restrict__ x,
                  const float* __restrict__ W0, const float* __restrict__ a0s,
                  const float* __restrict__ a0d, const float* __restrict__ b0,
                  const float* __restrict__ W1, const float* __restrict__ a1s,
                  const float* __restrict__ a1d, const float* __restrict__ b1,
                  const float* __restrict__ wg, const float* __restrict__ bg) {
    extern __shared__ float sm[];
    float* feats = sm;                         // 104 x FS
    float* hA    = sm + 104 * FS;
    float* hB    = hA + 104 * 64;
    float* norms = hB + 104 * 64;
    float* vsrc  = norms + 104;
    float* vdst  = vsrc + 104;
    unsigned* adjb = (unsigned*)(vdst + 104);  // 408
    int* tix = (int*)(adjb + 408);             // 104

    int b = blockIdx.x, tid = threadIdx.x, lane = tid & 31, wid = tid >> 5;

    for (int t = tid; t < NNODE; t += 256) tix[t] = g_topidx[b * NNODE + t];
    for (int t = tid; t < 408; t += 256) adjb[t] = 0u;
    __syncthreads();

    const float* xb = x + (size_t)b * CDIM * HWDIM;
    for (int t = tid; t < NNODE * CDIM; t += 256) {
        int n = t >> 8, c = t & 255;
        feats[n * FS + c] = xb[c * HWDIM + tix[n]];
    }
    __syncthreads();

    for (int n = wid; n < NNODE; n += 8) {
        float ss = 0.f;
        for (int c = lane; c < CDIM; c += 32) { float v = feats[n * FS + c]; ss += v * v; }
        ss = wrsum(ss);
        if (!lane) norms[n] = fmaxf(sqrtf(ss), 1e-12f);
    }
    __syncthreads();

    for (int t = tid; t < NNODE * NNODE; t += 256) {
        int i = t / NNODE, j = t - i * NNODE;
        if (j <= i) continue;
        const float* fi = feats + i * FS;
        const float* fj = feats + j * FS;
        float dot = 0.f;
        for (int c = 0; c < CDIM; c++) dot += fi[c] * fj[c];
        if (dot > 0.6f * norms[i] * norms[j]) {
            atomicOr(&adjb[i * 4 + (j >> 5)], 1u << (j & 31));
            atomicOr(&adjb[j * 4 + (i >> 5)], 1u << (i & 31));
        }
    }
    for (int t = tid; t < NNODE; t += 256)
        atomicOr(&adjb[t * 4 + (t >> 5)], 1u << (t & 31));
    __syncthreads();

    gat_linear<CDIM, FS>(feats, W0, hA, tid);               __syncthreads();
    gat_srcdst(hA, a0s, a0d, vsrc, vdst, wid, lane);        __syncthreads();
    gat_aggregate(hA, vsrc, vdst, adjb, b0, hB, wid, lane); __syncthreads();
    gat_linear<GD, GD>(hB, W1, hA, tid);                    __syncthreads();
    gat_srcdst(hA, a1s, a1d, vsrc, vdst, wid, lane);        __syncthreads();
    gat_aggregate(hA, vsrc, vdst, adjb, b1, hB, wid, lane); __syncthreads();

    for (int n = wid; n < NNODE; n += 8) {
        float v0 = hB[n * GD + lane], v1 = hB[n * GD + lane + 32];
#pragma unroll
        for (int hh = 0; hh < NH; hh++) {
            float p = v0 * __ldg(&wg[hh * GD + lane]) + v1 * __ldg(&wg[hh * GD + lane + 32]);
            p = wrsum(p);
            if (!lane)
                g_gw[(b * NNODE + n) * NH + hh] = 1.f / (1.f + __expf(-(p + __ldg(&bg[hh]))));
        }
    }
    for (int t = tid; t < 408; t += 256) g_adj[b * 408 + t] = adjb[t];
}

// ---- 4) QKV GEMM with packed f32x2 micro-kernel ----
__global__ __launch_bounds__(256)
void qkv_kernel(const float* __restrict__ x, const float* __restrict__ w) {
    __shared__ __align__(16) float As[16][64];
    __shared__ __align__(16) float Bs[16][68];
    int b = blockIdx.z;
    int p0 = blockIdx.x * 64, o0 = blockIdx.y * 64;
    int tid = threadIdx.x, tx = tid & 15, ty = tid >> 4;
    const float* xb = x + (size_t)b * CDIM * HWDIM;

    ull accp[2][4];   // packed over i-pairs x j
#pragma unroll
    for (int i = 0; i < 2; i++)
#pragma unroll
        for (int j = 0; j < 4; j++) accp[i][j] = 0ull;

    for (int c0 = 0; c0 < CDIM; c0 += 16) {
        {
            int c = tid >> 4, pv = (tid & 15) * 4;
            *(float4*)&As[c][pv] = *(const float4*)(xb + (size_t)(c0 + c) * HWDIM + p0 + pv);
        }
        {
            int o = tid >> 2, cv = (tid & 3) * 4;
            float4 wv = *(const float4*)(w + (size_t)(o0 + o) * CDIM + c0 + cv);
            Bs[cv + 0][o] = wv.x; Bs[cv + 1][o] = wv.y;
            Bs[cv + 2][o] = wv.z; Bs[cv + 3][o] = wv.w;
        }
        __syncthreads();
#pragma unroll
        for (int kk = 0; kk < 16; kk++) {
            ulonglong2 av2 = *(const ulonglong2*)&As[kk][tx * 4];  // (a0,a1),(a2,a3) free-packed
            float4 bv = *(const float4*)&Bs[kk][ty * 4];
            ull bp0 = pack2(bv.x, bv.x), bp1 = pack2(bv.y, bv.y);
            ull bp2 = pack2(bv.z, bv.z), bp3 = pack2(bv.w, bv.w);
            accp[0][0] = fma2(av2.x, bp0, accp[0][0]);
            accp[0][1] = fma2(av2.x, bp1, accp[0][1]);
            accp[0][2] = fma2(av2.x, bp2, accp[0][2]);
            accp[0][3] = fma2(av2.x, bp3, accp[0][3]);
            accp[1][0] = fma2(av2.y, bp0, accp[1][0]);
            accp[1][1] = fma2(av2.y, bp1, accp[1][1]);
            accp[1][2] = fma2(av2.y, bp2, accp[1][2]);
            accp[1][3] = fma2(av2.y, bp3, accp[1][3]);
        }
        __syncthreads();
    }
    float acc[4][4];
#pragma unroll
    for (int i2 = 0; i2 < 2; i2++)
#pragma unroll
        for (int j = 0; j < 4; j++) {
            float2 u = unpack2(accp[i2][j]);
            acc[2 * i2 + 0][j] = u.x;
            acc[2 * i2 + 1][j] = u.y;
        }
#pragma unroll
    for (int i = 0; i < 4; i++) {
        float4 st = make_float4(acc[i][0], acc[i][1], acc[i][2], acc[i][3]);
        *(float4*)(g_qkv + ((size_t)b * HWDIM + p0 + tx * 4 + i) * 768 + o0 + ty * 4) = st;
    }
}

// ---- 5) fused attention + graph modulation, packed f32x2 mainloop ----
#define TK 64
__global__ __launch_bounds__(128)
void attn_kernel() {
    __shared__ __align__(16) float Ks[TK * HD];
    __shared__ __align__(16) float Vs[TK * HD];
    __shared__ int   posk[TK];
    __shared__ float gwh[104];
    int b = blockIdx.z, h = blockIdx.y;
    int q0 = blockIdx.x * 256;
    int tid = threadIdx.x;
    int q1 = q0 + tid, q2 = q0 + 128 + tid;

    if (tid < NNODE) gwh[tid] = g_gw[(b * NNODE + tid) * NH + h];

    const float* qb = g_qkv + (size_t)b * HWDIM * 768;
    ull Q1p[16], Q2p[16], O1p[16], O2p[16];
    {
        const ulonglong2* p1 = (const ulonglong2*)(qb + (size_t)q1 * 768 + h * HD);
        const ulonglong2* p2 = (const ulonglong2*)(qb + (size_t)q2 * 768 + h * HD);
#pragma unroll
        for (int dd = 0; dd < 8; dd++) {
            ulonglong2 t1 = p1[dd]; Q1p[2*dd] = t1.x; Q1p[2*dd+1] = t1.y;
            ulonglong2 t2 = p2[dd]; Q2p[2*dd] = t2.x; Q2p[2*dd+1] = t2.y;
        }
    }
#pragma unroll
    for (int i = 0; i < 16; i++) { O1p[i] = 0ull; O2p[i] = 0ull; }

    int nq1 = g_posmap[b * HWDIM + q1];
    int nq2 = g_posmap[b * HWDIM + q2];
    __syncthreads();
    float gq1 = 0.f, gq2 = 0.f;
    unsigned A1[4] = {0,0,0,0}, A2[4] = {0,0,0,0};
    if (nq1 >= 0) {
        gq1 = gwh[nq1];
#pragma unroll
        for (int i = 0; i < 4; i++) A1[i] = g_adj[b * 408 + nq1 * 4 + i];
    }
    if (nq2 >= 0) {
        gq2 = gwh[nq2];
#pragma unroll
        for (int i = 0; i < 4; i++) A2[i] = g_adj[b * 408 + nq2 * 4 + i];
    }

    const float* kb = qb + 256 + h * HD;
    const float* vb = qb + 512 + h * HD;
    float l1 = 0.f, l2 = 0.f;

    for (int k0 = 0; k0 < HWDIM; k0 += TK) {
        __syncthreads();
#pragma unroll
        for (int u = 0; u < 4; u++) {
            int f4 = tid + u * 128;
            int r = f4 >> 3, dd = f4 & 7;
            ((float4*)Ks)[r * 8 + dd] = *(const float4*)(kb + (size_t)(k0 + r) * 768 + dd * 4);
            ((float4*)Vs)[r * 8 + dd] = *(const float4*)(vb + (size_t)(k0 + r) * 768 + dd * 4);
        }
        if (tid < TK) posk[tid] = g_posmap[b * HWDIM + k0 + tid];
        __syncthreads();

        for (int kk = 0; kk < TK; kk++) {
            const ulonglong2* K2 = (const ulonglong2*)(Ks + kk * HD);  // 8 x (2 packed pairs)
            ull a1 = 0ull, c1 = 0ull, a2 = 0ull, c2 = 0ull;
#pragma unroll
            for (int dd = 0; dd < 8; dd++) {
                ulonglong2 kv = K2[dd];
                a1 = fma2(Q1p[2*dd],   kv.x, a1);
                c1 = fma2(Q1p[2*dd+1], kv.y, c1);
                a2 = fma2(Q2p[2*dd],   kv.x, a2);
                c2 = fma2(Q2p[2*dd+1], kv.y, c2);
            }
            float2 f1 = unpack2(add2(a1, c1));
            float2 f2 = unpack2(add2(a2, c2));
            float s1 = (f1.x + f1.y) * SCALE;
            float s2 = (f2.x + f2.y) * SCALE;
            int nk = posk[kk];
            if (nk >= 0) {
                float gk = gwh[nk];
                unsigned w1 = (nk < 32) ? A1[0] : ((nk < 64) ? A1[1] : ((nk < 96) ? A1[2] : A1[3]));
                unsigned w2 = (nk < 32) ? A2[0] : ((nk < 64) ? A2[1] : ((nk < 96) ? A2[2] : A2[3]));
                if (nq1 >= 0 && ((w1 >> (nk & 31)) & 1u)) s1 += gq1 * gk;
                if (nq2 >= 0 && ((w2 >> (nk & 31)) & 1u)) s2 += gq2 * gk;
            }
            float e1 = __expf(s1), e2 = __expf(s2);   // |s| <= ~2.5: safe without max
            l1 += e1; l2 += e2;
            ull e1p = pack2(e1, e1), e2p = pack2(e2, e2);
            const ulonglong2* V2 = (const ulonglong2*)(Vs + kk * HD);
#pragma unroll
            for (int dd = 0; dd < 8; dd++) {
                ulonglong2 vv = V2[dd];
                O1p[2*dd]   = fma2(e1p, vv.x, O1p[2*dd]);
                O1p[2*dd+1] = fma2(e1p, vv.y, O1p[2*dd+1]);
                O2p[2*dd]   = fma2(e2p, vv.x, O2p[2*dd]);
                O2p[2*dd+1] = fma2(e2p, vv.y, O2p[2*dd+1]);
            }
        }
    }
    float inv1 = 1.f / l1, inv2 = 1.f / l2;
    float* o1p = g_attnout + ((size_t)b * HWDIM + q1) * CDIM + h * HD;
    float* o2p = g_attnout + ((size_t)b * HWDIM + q2) * CDIM + h * HD;
#pragma unroll
    for (int dd = 0; dd < 8; dd++) {
        float2 u0 = unpack2(O1p[2*dd]);
        float2 u1 = unpack2(O1p[2*dd+1]);
        *(float4*)(o1p + dd*4) = make_float4(u0.x*inv1, u0.y*inv1, u1.x*inv1, u1.y*inv1);
        float2 v0 = unpack2(O2p[2*dd]);
        float2 v1 = unpack2(O2p[2*dd+1]);
        *(float4*)(o2p + dd*4) = make_float4(v0.x*inv2, v0.y*inv2, v1.x*inv2, v1.y*inv2);
    }
}

// ---- 6) output projection (+bias), packed f32x2, output layout [B][C][HW] ----
__global__ __launch_bounds__(256)
void proj_kernel(const float* __restrict__ w, const float* __restrict__ bias,
                 float* __restrict__ out) {
    __shared__ __align__(16) float As[16][68];
    __shared__ __align__(16) float Bs[16][68];
    int b = blockIdx.z;
    int p0 = blockIdx.x * 64, o0 = blockIdx.y * 64;
    int tid = threadIdx.x, tx = tid & 15, ty = tid >> 4;
    const float* ab = g_attnout + (size_t)b * HWDIM * CDIM;

    ull accp[2][4];
#pragma unroll
    for (int i = 0; i < 2; i++)
#pragma unroll
        for (int j = 0; j < 4; j++) accp[i][j] = 0ull;

    for (int c0 = 0; c0 < CDIM; c0 += 16) {
        {
            int p = tid >> 2, cv = (tid & 3) * 4;
            float4 av = *(const float4*)(ab + (size_t)(p0 + p) * CDIM + c0 + cv);
            As[cv + 0][p] = av.x; As[cv + 1][p] = av.y;
            As[cv + 2][p] = av.z; As[cv + 3][p] = av.w;
        }
        {
            int o = tid >> 2, cv = (tid & 3) * 4;
            float4 wv = *(const float4*)(w + (size_t)(o0 + o) * CDIM + c0 + cv);
            Bs[cv + 0][o] = wv.x; Bs[cv + 1][o] = wv.y;
            Bs[cv + 2][o] = wv.z; Bs[cv + 3][o] = wv.w;
        }
        __syncthreads();
#pragma unroll
        for (int kk = 0; kk < 16; kk++) {
            ulonglong2 av2 = *(const ulonglong2*)&As[kk][tx * 4];
            float4 bv = *(const float4*)&Bs[kk][ty * 4];
            ull bp0 = pack2(bv.x, bv.x), bp1 = pack2(bv.y, bv.y);
            ull bp2 = pack2(bv.z, bv.z), bp3 = pack2(bv.w, bv.w);
            accp[0][0] = fma2(av2.x, bp0, accp[0][0]);
            accp[0][1] = fma2(av2.x, bp1, accp[0][1]);
            accp[0][2] = fma2(av2.x, bp2, accp[0][2]);
            accp[0][3] = fma2(av2.x, bp3, accp[0][3]);
            accp[1][0] = fma2(av2.y, bp0, accp[1][0]);
            accp[1][1] = fma2(av2.y, bp1, accp[1][1]);
            accp[1][2] = fma2(av2.y, bp2, accp[1][2]);
            accp[1][3] = fma2(av2.y, bp3, accp[1][3]);
        }
        __syncthreads();
    }
    float acc[4][4];
#pragma unroll
    for (int i2 = 0; i2 < 2; i2++)
#pragma unroll
        for (int j = 0; j < 4; j++) {
            float2 u = unpack2(accp[i2][j]);
            acc[2 * i2 + 0][j] = u.x;
            acc[2 * i2 + 1][j] = u.y;
        }
#pragma unroll
    for (int j = 0; j < 4; j++) {
        int o = o0 + ty * 4 + j;
        float bv = __ldg(&bias[o]);
        float4 st = make_float4(acc[0][j] + bv, acc[1][j] + bv, acc[2][j] + bv, acc[3][j] + bv);
        *(float4*)(out + ((size_t)b * CDIM + o) * HWDIM + p0 + tx * 4) = st;
    }
}

extern "C" void kernel_launch(void* const* d_in, const int* in_sizes, int n_in,
                              void* d_out, int out_size) {
    const float* x      = (const float*)d_in[0];
    const float* w_qkv  = (const float*)d_in[1];
    const float* w_proj = (const float*)d_in[2];
    const float* b_proj = (const float*)d_in[3];
    const float* g0W = (const float*)d_in[4];
    const float* g0s = (const float*)d_in[5];
    const float* g0d = (const float*)d_in[6];
    const float* g0b = (const float*)d_in[7];
    const float* g1W = (const float*)d_in[8];
    const float* g1s = (const float*)d_in[9];
    const float* g1d = (const float*)d_in[10];
    const float* g1b = (const float*)d_in[11];
    const float* wg  = (const float*)d_in[12];
    const float* bg  = (const float*)d_in[13];
    float* out = (float*)d_out;

    static bool attr_set = false;
    if (!attr_set) {
        cudaFuncSetAttribute(graph_kernel, cudaFuncAttributeMaxDynamicSharedMemorySize, GRAPH_SMEM);
        attr_set = true;
    }

    imp_kernel<<<dim3(HWDIM / 256, BATCH), 256>>>(x);
    topk_kernel<<<BATCH, 1024>>>();
    graph_kernel<<<BATCH, 256, GRAPH_SMEM>>>(x, g0W, g0s, g0d, g0b,
                                             g1W, g1s, g1d, g1b, wg, bg);
    qkv_kernel<<<dim3(HWDIM / 64, 768 / 64, BATCH), 256>>>(x, w_qkv);
    attn_kernel<<<dim3(HWDIM / 256, NH, BATCH), 128>>>();
    proj_kernel<<<dim3(HWDIM / 64, CDIM / 64, BATCH), 256>>>(w_proj, b_proj, out);
}

// round 17
// speedup vs baseline: 1.6299x; 1.0032x over previous
#include <cuda_runtime.h>

#define BATCH 8
#define CDIM  256
#define HWDIM 1024
#define NNODE 102
#define GD    64
#define NH    8
#define HD    32
#define SCALE 0.17677669529663687f

typedef unsigned long long ull;

__device__ float    g_importance[BATCH * HWDIM];
__device__ int      g_topidx[BATCH * NNODE];
__device__ int      g_posmap[BATCH * HWDIM];
__device__ float    g_gw[BATCH * NNODE * NH];
__device__ unsigned g_adj[BATCH * NNODE * 4];
__device__ float    g_qkv[(size_t)BATCH * HWDIM * 768];
__device__ float    g_attnout[(size_t)BATCH * HWDIM * CDIM];

__device__ __forceinline__ float wrsum(float v) {
#pragma unroll
    for (int o = 16; o; o >>= 1) v += __shfl_xor_sync(0xffffffffu, v, o);
    return v;
}

// ---- packed f32x2 helpers (FFMA2: only reachable via PTX) ----
__device__ __forceinline__ ull fma2(ull a, ull b, ull c) {
    ull d;
    asm("fma.rn.f32x2 %0, %1, %2, %3;" : "=l"(d) : "l"(a), "l"(b), "l"(c));
    return d;
}
__device__ __forceinline__ ull add2(ull a, ull b) {
    ull d;
    asm("add.rn.f32x2 %0, %1, %2;" : "=l"(d) : "l"(a), "l"(b));
    return d;
}
__device__ __forceinline__ ull pack2(float x, float y) {
    ull d;
    asm("mov.b64 %0, {%1, %2};" : "=l"(d) : "f"(x), "f"(y));
    return d;
}
__device__ __forceinline__ float2 unpack2(ull v) {
    float x, y;
    asm("mov.b64 {%0, %1}, %2;" : "=f"(x), "=f"(y) : "l"(v));
    return make_float2(x, y);
}

// ---- 1) importance = channel variance (ordering only; constant factor dropped) ----
__global__ void imp_kernel(const float* __restrict__ x) {
    int b = blockIdx.y;
    int p = blockIdx.x * 256 + threadIdx.x;
    const float* xp = x + (size_t)b * CDIM * HWDIM + p;
    float s = 0.f;
    for (int c = 0; c < CDIM; c++) s += xp[c * HWDIM];
    float mean = s * (1.f / 256.f);
    float ss = 0.f;
    for (int c = 0; c < CDIM; c++) { float d = xp[c * HWDIM] - mean; ss += d * d; }
    g_importance[b * HWDIM + p] = ss;
}

// ---- 2) top-102 per batch via bitonic sort (descending) ----
__global__ void topk_kernel() {
    __shared__ float sv[1024];
    __shared__ int   si[1024];
    int b = blockIdx.x, tid = threadIdx.x;
    sv[tid] = g_importance[b * HWDIM + tid];
    si[tid] = tid;
    g_posmap[b * HWDIM + tid] = -1;
    __syncthreads();
    for (int k = 2; k <= 1024; k <<= 1)
        for (int j = k >> 1; j > 0; j >>= 1) {
            int ixj = tid ^ j;
            if (ixj > tid) {
                bool up = ((tid & k) == 0);
                float va = sv[tid], vb = sv[ixj];
                bool sw = up ? (va < vb) : (va > vb);
                if (sw) {
                    sv[tid] = vb; sv[ixj] = va;
                    int t = si[tid]; si[tid] = si[ixj]; si[ixj] = t;
                }
            }
            __syncthreads();
        }
    if (tid < NNODE) {
        g_topidx[b * NNODE + tid] = si[tid];
        g_posmap[b * HWDIM + si[tid]] = tid;
    }
}

// ---- 3) graph kernel: gather, adjacency, 2x GAT, gate ----
#define FS 257
#define GRAPH_SMEM ((104*FS + 104*64*2 + 104*3)*4 + 408*4 + 104*4)

template<int CIN, int ISTR>
__device__ __forceinline__ void gat_linear(const float* __restrict__ in,
                                           const float* __restrict__ W,
                                           float* __restrict__ out, int tid) {
    int f = tid & 63, grp = tid >> 6;
    for (int nb = grp * 8; nb < NNODE; nb += 32) {
        float acc[8] = {0,0,0,0,0,0,0,0};
        for (int c = 0; c < CIN; c++) {
            float w = __ldg(&W[c * GD + f]);
            const float* ip = in + c;
#pragma unroll
            for (int u = 0; u < 8; u++) acc[u] += ip[(nb + u) * ISTR] * w;
        }
#pragma unroll
        for (int u = 0; u < 8; u++)
            if (nb + u < NNODE) out[(nb + u) * GD + f] = acc[u];
    }
}

__device__ __forceinline__ void gat_srcdst(const float* __restrict__ h,
                                           const float* __restrict__ asw,
                                           const float* __restrict__ adw,
                                           float* __restrict__ vsrc, float* __restrict__ vdst,
                                           int wid, int lane) {
    for (int n = wid; n < NNODE; n += 8) {
        float h0 = h[n * GD + lane], h1 = h[n * GD + lane + 32];
        float ps = h0 * __ldg(&asw[lane]) + h1 * __ldg(&asw[lane + 32]);
        float pd = h0 * __ldg(&adw[lane]) + h1 * __ldg(&adw[lane + 32]);
        ps = wrsum(ps); pd = wrsum(pd);
        if (!lane) { vsrc[n] = ps; vdst[n] = pd; }
    }
}

__device__ __forceinline__ void gat_aggregate(const float* __restrict__ h,
                                              const float* __restrict__ vsrc,
                                              const float* __restrict__ vdst,
                                              const unsigned* __restrict__ adjb,
                                              const float* __restrict__ bias,
                                              float* __restrict__ out,
                                              int wid, int lane) {
    for (int n = wid; n < NNODE; n += 8) {
        float dn = vdst[n];
        unsigned r0 = adjb[n*4+0], r1 = adjb[n*4+1], r2 = adjb[n*4+2], r3 = adjb[n*4+3];
        float den = 0.f, a0 = 0.f, a1 = 0.f;
        for (int j = 0; j < NNODE; j++) {
            unsigned w = (j < 32) ? r0 : ((j < 64) ? r1 : ((j < 96) ? r2 : r3));
            if ((w >> (j & 31)) & 1u) {
                float lg = dn + vsrc[j];
                lg = lg > 0.f ? lg : 0.2f * lg;
                float e = __expf(lg);
                den += e;
                a0 += e * h[j * GD + lane];
                a1 += e * h[j * GD + lane + 32];
            }
        }
        float inv = 1.f / den;
        float o0 = a0 * inv + __ldg(&bias[lane]);
        float o1 = a1 * inv + __ldg(&bias[lane + 32]);
        out[n * GD + lane]      = fmaxf(o0, 0.f);
        out[n * GD + lane + 32] = fmaxf(o1, 0.f);
    }
}

__global__ __launch_bounds__(256)
void graph_kernel(const float* __restrict__ x,
                  const float* __restrict__ W0, const float* __restrict__ a0s,
                  const float* __restrict__ a0d, const float* __restrict__ b0,
                  const float* __restrict__ W1, const float* __restrict__ a1s,
                  const float* __restrict__ a1d, const float* __restrict__ b1,
                  const float* __restrict__ wg, const float* __restrict__ bg) {
    extern __shared__ float sm[];
    float* feats = sm;                         // 104 x FS
    float* hA    = sm + 104 * FS;
    float* hB    = hA + 104 * 64;
    float* norms = hB + 104 * 64;
    float* vsrc  = norms + 104;
    float* vdst  = vsrc + 104;
    unsigned* adjb = (unsigned*)(vdst + 104);  // 408
    int* tix = (int*)(adjb + 408);             // 104

    int b = blockIdx.x, tid = threadIdx.x, lane = tid & 31, wid = tid >> 5;

    for (int t = tid; t < NNODE; t += 256) tix[t] = g_topidx[b * NNODE + t];
    for (int t = tid; t < 408; t += 256) adjb[t] = 0u;
    __syncthreads();

    const float* xb = x + (size_t)b * CDIM * HWDIM;
    for (int t = tid; t < NNODE * CDIM; t += 256) {
        int n = t >> 8, c = t & 255;
        feats[n * FS + c] = xb[c * HWDIM + tix[n]];
    }
    __syncthreads();

    for (int n = wid; n < NNODE; n += 8) {
        float ss = 0.f;
        for (int c = lane; c < CDIM; c += 32) { float v = feats[n * FS + c]; ss += v * v; }
        ss = wrsum(ss);
        if (!lane) norms[n] = fmaxf(sqrtf(ss), 1e-12f);
    }
    __syncthreads();

    for (int t = tid; t < NNODE * NNODE; t += 256) {
        int i = t / NNODE, j = t - i * NNODE;
        if (j <= i) continue;
        const float* fi = feats + i * FS;
        const float* fj = feats + j * FS;
        float dot = 0.f;
        for (int c = 0; c < CDIM; c++) dot += fi[c] * fj[c];
        if (dot > 0.6f * norms[i] * norms[j]) {
            atomicOr(&adjb[i * 4 + (j >> 5)], 1u << (j & 31));
            atomicOr(&adjb[j * 4 + (i >> 5)], 1u << (i & 31));
        }
    }
    for (int t = tid; t < NNODE; t += 256)
        atomicOr(&adjb[t * 4 + (t >> 5)], 1u << (t & 31));
    __syncthreads();

    gat_linear<CDIM, FS>(feats, W0, hA, tid);               __syncthreads();
    gat_srcdst(hA, a0s, a0d, vsrc, vdst, wid, lane);        __syncthreads();
    gat_aggregate(hA, vsrc, vdst, adjb, b0, hB, wid, lane); __syncthreads();
    gat_linear<GD, GD>(hB, W1, hA, tid);                    __syncthreads();
    gat_srcdst(hA, a1s, a1d, vsrc, vdst, wid, lane);        __syncthreads();
    gat_aggregate(hA, vsrc, vdst, adjb, b1, hB, wid, lane); __syncthreads();

    for (int n = wid; n < NNODE; n += 8) {
        float v0 = hB[n * GD + lane], v1 = hB[n * GD + lane + 32];
#pragma unroll
        for (int hh = 0; hh < NH; hh++) {
            float p = v0 * __ldg(&wg[hh * GD + lane]) + v1 * __ldg(&wg[hh * GD + lane + 32]);
            p = wrsum(p);
            if (!lane)
                g_gw[(b * NNODE + n) * NH + hh] = 1.f / (1.f + __expf(-(p + __ldg(&bg[hh]))));
        }
    }
    for (int t = tid; t < 408; t += 256) g_adj[b * 408 + t] = adjb[t];
}

// ---- 4) QKV GEMM with packed f32x2 micro-kernel ----
__global__ __launch_bounds__(256)
void qkv_kernel(const float* __restrict__ x, const float* __restrict__ w) {
    __shared__ __align__(16) float As[16][64];
    __shared__ __align__(16) float Bs[16][68];
    int b = blockIdx.z;
    int p0 = blockIdx.x * 64, o0 = blockIdx.y * 64;
    int tid = threadIdx.x, tx = tid & 15, ty = tid >> 4;
    const float* xb = x + (size_t)b * CDIM * HWDIM;

    ull accp[2][4];   // packed over i-pairs x j
#pragma unroll
    for (int i = 0; i < 2; i++)
#pragma unroll
        for (int j = 0; j < 4; j++) accp[i][j] = 0ull;

    for (int c0 = 0; c0 < CDIM; c0 += 16) {
        {
            int c = tid >> 4, pv = (tid & 15) * 4;
            *(float4*)&As[c][pv] = *(const float4*)(xb + (size_t)(c0 + c) * HWDIM + p0 + pv);
        }
        {
            int o = tid >> 2, cv = (tid & 3) * 4;
            float4 wv = *(const float4*)(w + (size_t)(o0 + o) * CDIM + c0 + cv);
            Bs[cv + 0][o] = wv.x; Bs[cv + 1][o] = wv.y;
            Bs[cv + 2][o] = wv.z; Bs[cv + 3][o] = wv.w;
        }
        __syncthreads();
#pragma unroll
        for (int kk = 0; kk < 16; kk++) {
            ulonglong2 av2 = *(const ulonglong2*)&As[kk][tx * 4];  // (a0,a1),(a2,a3) free-packed
            float4 bv = *(const float4*)&Bs[kk][ty * 4];
            ull bp0 = pack2(bv.x, bv.x), bp1 = pack2(bv.y, bv.y);
            ull bp2 = pack2(bv.z, bv.z), bp3 = pack2(bv.w, bv.w);
            accp[0][0] = fma2(av2.x, bp0, accp[0][0]);
            accp[0][1] = fma2(av2.x, bp1, accp[0][1]);
            accp[0][2] = fma2(av2.x, bp2, accp[0][2]);
            accp[0][3] = fma2(av2.x, bp3, accp[0][3]);
            accp[1][0] = fma2(av2.y, bp0, accp[1][0]);
            accp[1][1] = fma2(av2.y, bp1, accp[1][1]);
            accp[1][2] = fma2(av2.y, bp2, accp[1][2]);
            accp[1][3] = fma2(av2.y, bp3, accp[1][3]);
        }
        __syncthreads();
    }
    float acc[4][4];
#pragma unroll
    for (int i2 = 0; i2 < 2; i2++)
#pragma unroll
        for (int j = 0; j < 4; j++) {
            float2 u = unpack2(accp[i2][j]);
            acc[2 * i2 + 0][j] = u.x;
            acc[2 * i2 + 1][j] = u.y;
        }
#pragma unroll
    for (int i = 0; i < 4; i++) {
        float4 st = make_float4(acc[i][0], acc[i][1], acc[i][2], acc[i][3]);
        *(float4*)(g_qkv + ((size_t)b * HWDIM + p0 + tx * 4 + i) * 768 + o0 + ty * 4) = st;
    }
}

// ---- 5) fused attention + graph modulation, packed f32x2 mainloop ----
#define TK 64
__global__ __launch_bounds__(128)
void attn_kernel() {
    __shared__ __align__(16) float Ks[TK * HD];
    __shared__ __align__(16) float Vs[TK * HD];
    __shared__ int   posk[TK];
    __shared__ float gwh[104];
    int b = blockIdx.z, h = blockIdx.y;
    int q0 = blockIdx.x * 256;
    int tid = threadIdx.x;
    int q1 = q0 + tid, q2 = q0 + 128 + tid;

    if (tid < NNODE) gwh[tid] = g_gw[(b * NNODE + tid) * NH + h];

    const float* qb = g_qkv + (size_t)b * HWDIM * 768;
    ull Q1p[16], Q2p[16], O1p[16], O2p[16];
    {
        const ulonglong2* p1 = (const ulonglong2*)(qb + (size_t)q1 * 768 + h * HD);
        const ulonglong2* p2 = (const ulonglong2*)(qb + (size_t)q2 * 768 + h * HD);
#pragma unroll
        for (int dd = 0; dd < 8; dd++) {
            ulonglong2 t1 = p1[dd]; Q1p[2*dd] = t1.x; Q1p[2*dd+1] = t1.y;
            ulonglong2 t2 = p2[dd]; Q2p[2*dd] = t2.x; Q2p[2*dd+1] = t2.y;
        }
    }
#pragma unroll
    for (int i = 0; i < 16; i++) { O1p[i] = 0ull; O2p[i] = 0ull; }

    int nq1 = g_posmap[b * HWDIM + q1];
    int nq2 = g_posmap[b * HWDIM + q2];
    __syncthreads();
    float gq1 = 0.f, gq2 = 0.f;
    unsigned A1[4] = {0,0,0,0}, A2[4] = {0,0,0,0};
    if (nq1 >= 0) {
        gq1 = gwh[nq1];
#pragma unroll
        for (int i = 0; i < 4; i++) A1[i] = g_adj[b * 408 + nq1 * 4 + i];
    }
    if (nq2 >= 0) {
        gq2 = gwh[nq2];
#pragma unroll
        for (int i = 0; i < 4; i++) A2[i] = g_adj[b * 408 + nq2 * 4 + i];
    }

    const float* kb = qb + 256 + h * HD;
    const float* vb = qb + 512 + h * HD;
    float l1 = 0.f, l2 = 0.f;

    for (int k0 = 0; k0 < HWDIM; k0 += TK) {
        __syncthreads();
#pragma unroll
        for (int u = 0; u < 4; u++) {
            int f4 = tid + u * 128;
            int r = f4 >> 3, dd = f4 & 7;
            ((float4*)Ks)[r * 8 + dd] = *(const float4*)(kb + (size_t)(k0 + r) * 768 + dd * 4);
            ((float4*)Vs)[r * 8 + dd] = *(const float4*)(vb + (size_t)(k0 + r) * 768 + dd * 4);
        }
        if (tid < TK) posk[tid] = g_posmap[b * HWDIM + k0 + tid];
        __syncthreads();

        for (int kk = 0; kk < TK; kk++) {
            const ulonglong2* K2 = (const ulonglong2*)(Ks + kk * HD);  // 8 x (2 packed pairs)
            ull a1 = 0ull, c1 = 0ull, a2 = 0ull, c2 = 0ull;
#pragma unroll
            for (int dd = 0; dd < 8; dd++) {
                ulonglong2 kv = K2[dd];
                a1 = fma2(Q1p[2*dd],   kv.x, a1);
                c1 = fma2(Q1p[2*dd+1], kv.y, c1);
                a2 = fma2(Q2p[2*dd],   kv.x, a2);
                c2 = fma2(Q2p[2*dd+1], kv.y, c2);
            }
            float2 f1 = unpack2(add2(a1, c1));
            float2 f2 = unpack2(add2(a2, c2));
            float s1 = (f1.x + f1.y) * SCALE;
            float s2 = (f2.x + f2.y) * SCALE;
            int nk = posk[kk];
            if (nk >= 0) {
                float gk = gwh[nk];
                unsigned w1 = (nk < 32) ? A1[0] : ((nk < 64) ? A1[1] : ((nk < 96) ? A1[2] : A1[3]));
                unsigned w2 = (nk < 32) ? A2[0] : ((nk < 64) ? A2[1] : ((nk < 96) ? A2[2] : A2[3]));
                if (nq1 >= 0 && ((w1 >> (nk & 31)) & 1u)) s1 += gq1 * gk;
                if (nq2 >= 0 && ((w2 >> (nk & 31)) & 1u)) s2 += gq2 * gk;
            }
            float e1 = __expf(s1), e2 = __expf(s2);   // |s| <= ~2.5: safe without max
            l1 += e1; l2 += e2;
            ull e1p = pack2(e1, e1), e2p = pack2(e2, e2);
            const ulonglong2* V2 = (const ulonglong2*)(Vs + kk * HD);
#pragma unroll
            for (int dd = 0; dd < 8; dd++) {
                ulonglong2 vv = V2[dd];
                O1p[2*dd]   = fma2(e1p, vv.x, O1p[2*dd]);
                O1p[2*dd+1] = fma2(e1p, vv.y, O1p[2*dd+1]);
                O2p[2*dd]   = fma2(e2p, vv.x, O2p[2*dd]);
                O2p[2*dd+1] = fma2(e2p, vv.y, O2p[2*dd+1]);
            }
        }
    }
    float inv1 = 1.f / l1, inv2 = 1.f / l2;
    float* o1p = g_attnout + ((size_t)b * HWDIM + q1) * CDIM + h * HD;
    float* o2p = g_attnout + ((size_t)b * HWDIM + q2) * CDIM + h * HD;
#pragma unroll
    for (int dd = 0; dd < 8; dd++) {
        float2 u0 = unpack2(O1p[2*dd]);
        float2 u1 = unpack2(O1p[2*dd+1]);
        *(float4*)(o1p + dd*4) = make_float4(u0.x*inv1, u0.y*inv1, u1.x*inv1, u1.y*inv1);
        float2 v0 = unpack2(O2p[2*dd]);
        float2 v1 = unpack2(O2p[2*dd+1]);
        *(float4*)(o2p + dd*4) = make_float4(v0.x*inv2, v0.y*inv2, v1.x*inv2, v1.y*inv2);
    }
}

// ---- 6) output projection (+bias), packed f32x2, output layout [B][C][HW] ----
__global__ __launch_bounds__(256)
void proj_kernel(const float* __restrict__ w, const float* __restrict__ bias,
                 float* __restrict__ out) {
    __shared__ __align__(16) float As[16][68];
    __shared__ __align__(16) float Bs[16][68];
    int b = blockIdx.z;
    int p0 = blockIdx.x * 64, o0 = blockIdx.y * 64;
    int tid = threadIdx.x, tx = tid & 15, ty = tid >> 4;
    const float* ab = g_attnout + (size_t)b * HWDIM * CDIM;

    ull accp[2][4];
#pragma unroll
    for (int i = 0; i < 2; i++)
#pragma unroll
        for (int j = 0; j < 4; j++) accp[i][j] = 0ull;

    for (int c0 = 0; c0 < CDIM; c0 += 16) {
        {
            int p = tid >> 2, cv = (tid & 3) * 4;
            float4 av = *(const float4*)(ab + (size_t)(p0 + p) * CDIM + c0 + cv);
            As[cv + 0][p] = av.x; As[cv + 1][p] = av.y;
            As[cv + 2][p] = av.z; As[cv + 3][p] = av.w;
        }
        {
            int o = tid >> 2, cv = (tid & 3) * 4;
            float4 wv = *(const float4*)(w + (size_t)(o0 + o) * CDIM + c0 + cv);
            Bs[cv + 0][o] = wv.x; Bs[cv + 1][o] = wv.y;
            Bs[cv + 2][o] = wv.z; Bs[cv + 3][o] = wv.w;
        }
        __syncthreads();
#pragma unroll
        for (int kk = 0; kk < 16; kk++) {
            ulonglong2 av2 = *(const ulonglong2*)&As[kk][tx * 4];
            float4 bv = *(const float4*)&Bs[kk][ty * 4];
            ull bp0 = pack2(bv.x, bv.x), bp1 = pack2(bv.y, bv.y);
            ull bp2 = pack2(bv.z, bv.z), bp3 = pack2(bv.w, bv.w);
            accp[0][0] = fma2(av2.x, bp0, accp[0][0]);
            accp[0][1] = fma2(av2.x, bp1, accp[0][1]);
            accp[0][2] = fma2(av2.x, bp2, accp[0][2]);
            accp[0][3] = fma2(av2.x, bp3, accp[0][3]);
            accp[1][0] = fma2(av2.y, bp0, accp[1][0]);
            accp[1][1] = fma2(av2.y, bp1, accp[1][1]);
            accp[1][2] = fma2(av2.y, bp2, accp[1][2]);
            accp[1][3] = fma2(av2.y, bp3, accp[1][3]);
        }
        __syncthreads();
    }
    float acc[4][4];
#pragma unroll
    for (int i2 = 0; i2 < 2; i2++)
#pragma unroll
        for (int j = 0; j < 4; j++) {
            float2 u = unpack2(accp[i2][j]);
            acc[2 * i2 + 0][j] = u.x;
            acc[2 * i2 + 1][j] = u.y;
        }
#pragma unroll
    for (int j = 0; j < 4; j++) {
        int o = o0 + ty * 4 + j;
        float bv = __ldg(&bias[o]);
        float4 st = make_float4(acc[0][j] + bv, acc[1][j] + bv, acc[2][j] + bv, acc[3][j] + bv);
        *(float4*)(out + ((size_t)b * CDIM + o) * HWDIM + p0 + tx * 4) = st;
    }
}

extern "C" void kernel_launch(void* const* d_in, const int* in_sizes, int n_in,
                              void* d_out, int out_size) {
    const float* x      = (const float*)d_in[0];
    const float* w_qkv  = (const float*)d_in[1];
    const float* w_proj = (const float*)d_in[2];
    const float* b_proj = (const float*)d_in[3];
    const float* g0W = (const float*)d_in[4];
    const float* g0s = (const float*)d_in[5];
    const float* g0d = (const float*)d_in[6];
    const float* g0b = (const float*)d_in[7];
    const float* g1W = (const float*)d_in[8];
    const float* g1s = (const float*)d_in[9];
    const float* g1d = (const float*)d_in[10];
    const float* g1b = (const float*)d_in[11];
    const float* wg  = (const float*)d_in[12];
    const float* bg  = (const float*)d_in[13];
    float* out = (float*)d_out;

    static bool attr_set = false;
    if (!attr_set) {
        cudaFuncSetAttribute(graph_kernel, cudaFuncAttributeMaxDynamicSharedMemorySize, GRAPH_SMEM);
        attr_set = true;
    }

    imp_kernel<<<dim3(HWDIM / 256, BATCH), 256>>>(x);
    topk_kernel<<<BATCH, 1024>>>();
    graph_kernel<<<BATCH, 256, GRAPH_SMEM>>>(x, g0W, g0s, g0d, g0b,
                                             g1W, g1s, g1d, g1b, wg, bg);
    qkv_kernel<<<dim3(HWDIM / 64, 768 / 64, BATCH), 256>>>(x, w_qkv);
    attn_kernel<<<dim3(HWDIM / 256, NH, BATCH), 128>>>();
    proj_kernel<<<dim3(HWDIM / 64, CDIM / 64, BATCH), 256>>>(w_proj, b_proj, out);
}